// round 8
// baseline (speedup 1.0000x reference)
#include <cuda_runtime.h>
#include <cstdint>

#define GRIDW 480
#define NPTS 100000
#define PTOT 400000
#define NCELL (4*GRIDW*GRIDW)      // 921600
#define NSM 148
#define NTHR 384
#define NWARPS (NSM*12)            // 1776
#define NGROUP32 (PTOT/32)         // 12500 warp-groups of 32 points

// ---------------- smem layout (u32 offsets) ----------------
#define SW2 0        // W2 B-frags fp16: 4nc x 8ks x 8nt x 64 = 16384 u32
#define SW3 16384    // W3 B-frags fp16: 4nc x 4kt x 8nt x 64 = 8192 u32
#define SW1 24576    // 3*128 f32
#define SB1 24960    // 128
#define SB2 25088    // 256
#define SB3 25344    // 64
#define SMEM_U32 25408
#define SMEM_BYTES (SMEM_U32*4)    // 101632 B

// ---------------- device scratch ----------------
__device__ int g_cnt[NCELL];      // zero at load; self-resetting (scan1 clears)
__device__ int g_rank[NCELL];     // scan1: partial|flags ; scan3: (rank<<1)|solo
__device__ int g_bsum[1024];

// ---------------- helpers ----------------
__device__ __forceinline__ uint32_t f2h2(float lo, float hi) {
    uint32_t r;
    asm("cvt.rn.f16x2.f32 %0, %1, %2;" : "=r"(r) : "f"(hi), "f"(lo));
    return r;
}
__device__ __forceinline__ unsigned short f2h(float f) {
    unsigned short h;
    asm("cvt.rn.f16.f32 %0, %1;" : "=h"(h) : "f"(f));
    return h;
}
__device__ __forceinline__ void mma16(float* d, const uint32_t* a, uint32_t b0, uint32_t b1) {
    asm volatile("mma.sync.aligned.m16n8k16.row.col.f32.f16.f16.f32 "
        "{%0,%1,%2,%3},{%4,%5,%6,%7},{%8,%9},{%0,%1,%2,%3};"
        : "+f"(d[0]), "+f"(d[1]), "+f"(d[2]), "+f"(d[3])
        : "r"(a[0]), "r"(a[1]), "r"(a[2]), "r"(a[3]), "r"(b0), "r"(b1));
}
__device__ __forceinline__ void atomic_fmax(float* addr, float v) {
    if (v >= 0.0f) atomicMax((int*)addr, __float_as_int(v));
    else atomicMin((unsigned int*)addr, __float_as_uint(v));
}

// ---------------- small kernels ----------------
__global__ void k_mark(const int* __restrict__ xy) {
    int p = blockIdx.x * blockDim.x + threadIdx.x;
    if (p < PTOT) {
        int2 v = ((const int2*)xy)[p];
        int b = p / NPTS;
        atomicAdd(&g_cnt[(b * GRIDW + v.x) * GRIDW + v.y], 1);
    }
}

// per-block exclusive scan of occupancy; packs occ/solo flags; zeroes g_cnt for next replay
__global__ void k_scan1() {
    __shared__ int ws[32];
    int i = blockIdx.x * 1024 + threadIdx.x;
    int lane = threadIdx.x & 31, wid = threadIdx.x >> 5;
    int c = g_cnt[i];
    if (c) g_cnt[i] = 0;                    // self-reset (write only if dirty)
    int v = (c != 0);
    unsigned int m = __ballot_sync(0xffffffffu, v);
    int excl = __popc(m & ((1u << lane) - 1u));
    if (lane == 31) ws[wid] = excl + v;
    __syncthreads();
    if (wid == 0) {
        int x = ws[lane];
        #pragma unroll
        for (int d = 1; d < 32; d <<= 1) {
            int o = __shfl_up_sync(0xffffffffu, x, d);
            if (lane >= d) x += o;
        }
        ws[lane] = x;
    }
    __syncthreads();
    int partial = excl + (wid ? ws[wid - 1] : 0);
    g_rank[i] = partial | (v << 16) | ((c == 1) << 17);
    if (threadIdx.x == 1023) g_bsum[blockIdx.x] = ws[31];
}

// finalize ranks (block offset computed inline from g_bsum), write unq rows,
// and -inf-init pooled rows of non-solo voxels (warp-cooperative, coalesced).
__global__ void k_scan3(float* unq_out, uint2* pooled) {
    __shared__ int ws[32];
    __shared__ int s_off;
    int t = threadIdx.x;
    int lane = t & 31, wid = t >> 5;

    int v = (t < blockIdx.x && t < 900) ? g_bsum[t] : 0;
    #pragma unroll
    for (int d = 16; d > 0; d >>= 1)
        v += __shfl_xor_sync(0xffffffffu, v, d);
    if (lane == 0) ws[wid] = v;
    __syncthreads();
    if (wid == 0) {
        int x = ws[lane];
        #pragma unroll
        for (int d = 16; d > 0; d >>= 1)
            x += __shfl_xor_sync(0xffffffffu, x, d);
        if (lane == 0) s_off = x;
    }
    __syncthreads();
    int off = s_off;

    int i = blockIdx.x * 1024 + t;
    int packed = g_rank[i];
    int occ = (packed >> 16) & 1;
    int solo = (packed >> 17) & 1;
    int r = (packed & 0xFFFF) + off;
    if (occ) {
        g_rank[i] = (r << 1) | solo;
        if (unq_out) {
            int b = i / (GRIDW * GRIDW);
            int rem = i - b * GRIDW * GRIDW;
            unq_out[3 * r + 0] = (float)b;
            unq_out[3 * r + 1] = (float)(rem / GRIDW);
            unq_out[3 * r + 2] = (float)(rem % GRIDW);
        }
    }
    unsigned int nm = __ballot_sync(0xffffffffu, occ && !solo);
    uint2 ninf = make_uint2(0xff800000u, 0xff800000u);
    while (nm) {
        int src = __ffs(nm) - 1;
        nm &= nm - 1;
        int rr = __shfl_sync(0xffffffffu, r, src);
        pooled[(size_t)rr * 32 + lane] = ninf;
    }
}

// ---------------- fused fp16 mma.sync MLP, M=32 per warp ----------------
__global__ void __launch_bounds__(NTHR, 1)
k_mlp(const float* __restrict__ pt_fea, const int* __restrict__ xy,
      const float* __restrict__ W1g, const float* __restrict__ b1g,
      const float* __restrict__ W2g, const float* __restrict__ b2g,
      const float* __restrict__ W3g, const float* __restrict__ b3g,
      float* __restrict__ pooled) {
    extern __shared__ uint32_t sm[];
    float* smf = (float*)sm;
    int t = threadIdx.x;

    // ---- stage W2 as fp16 B-frags: sm[SW2 + ((nc*8+ks)*8+nt)*64 + lane*2 + j] ----
    for (int idx = t; idx < 16384; idx += NTHR) {
        int j = idx & 1, lane = (idx >> 1) & 31, nt = (idx >> 6) & 7,
            ks = (idx >> 9) & 7, nc = idx >> 12;
        int k = ks * 16 + (lane & 3) * 2 + j * 8;
        int n = nc * 64 + nt * 8 + (lane >> 2);
        sm[SW2 + idx] = (uint32_t)f2h(W2g[k * 256 + n]) |
                        ((uint32_t)f2h(W2g[(k + 1) * 256 + n]) << 16);
    }
    // ---- stage W3 as fp16 B-frags: sm[SW3 + ((nc*4+kt)*8+nt)*64 + lane*2 + j] ----
    for (int idx = t; idx < 8192; idx += NTHR) {
        int j = idx & 1, lane = (idx >> 1) & 31, nt = (idx >> 6) & 7,
            kt = (idx >> 9) & 3, nc = idx >> 11;
        int k = nc * 64 + kt * 16 + (lane & 3) * 2 + j * 8;
        int n = nt * 8 + (lane >> 2);
        sm[SW3 + idx] = (uint32_t)f2h(W3g[k * 64 + n]) |
                        ((uint32_t)f2h(W3g[(k + 1) * 64 + n]) << 16);
    }
    for (int i = t; i < 384; i += NTHR) smf[SW1 + i] = W1g[i];
    if (t < 128) smf[SB1 + t] = b1g[t];
    if (t < 64) { smf[SB2 + t] = b2g[t]; smf[SB2 + 64 + t] = b2g[64 + t];
                  smf[SB2 + 128 + t] = b2g[128 + t]; smf[SB2 + 192 + t] = b2g[192 + t];
                  smf[SB3 + t] = b3g[t]; }
    __syncthreads();

    const int lane = t & 31;
    const int gq = lane >> 2, tig = lane & 3;
    const int warp = blockIdx.x * (NTHR / 32) + (t >> 5);

    for (int grp = warp; grp < NGROUP32; grp += NWARPS) {
        int base = grp * 32;
        int p0 = base + gq, p1 = p0 + 8, p2 = p0 + 16, p3 = p0 + 24;
        int2 v0 = ((const int2*)xy)[p0];
        int2 v1 = ((const int2*)xy)[p1];
        int2 v2 = ((const int2*)xy)[p2];
        int2 v3 = ((const int2*)xy)[p3];
        int r0 = g_rank[((p0 / NPTS) * GRIDW + v0.x) * GRIDW + v0.y];
        int r1 = g_rank[((p1 / NPTS) * GRIDW + v1.x) * GRIDW + v1.y];
        int r2 = g_rank[((p2 / NPTS) * GRIDW + v2.x) * GRIDW + v2.y];
        int r3 = g_rank[((p3 / NPTS) * GRIDW + v3.x) * GRIDW + v3.y];
        float x00 = pt_fea[p0 * 3], x01 = pt_fea[p0 * 3 + 1], x02 = pt_fea[p0 * 3 + 2];
        float x10 = pt_fea[p1 * 3], x11 = pt_fea[p1 * 3 + 1], x12 = pt_fea[p1 * 3 + 2];
        float x20 = pt_fea[p2 * 3], x21 = pt_fea[p2 * 3 + 1], x22 = pt_fea[p2 * 3 + 2];
        float x30 = pt_fea[p3 * 3], x31 = pt_fea[p3 * 3 + 1], x32 = pt_fea[p3 * 3 + 2];

        // ---- layer 1 -> two m16 A-tile fragment sets ----
        uint32_t A0[8][4], A1[8][4];
        #pragma unroll
        for (int ks = 0; ks < 8; ks++) {
            #pragma unroll
            for (int h = 0; h < 2; h++) {
                int c = ks * 16 + tig * 2 + h * 8;
                float wa0 = smf[SW1 + c],       wa1 = smf[SW1 + c + 1];
                float wb0 = smf[SW1 + 128 + c], wb1 = smf[SW1 + 128 + c + 1];
                float wc0 = smf[SW1 + 256 + c], wc1 = smf[SW1 + 256 + c + 1];
                float ba = smf[SB1 + c], bb = smf[SB1 + c + 1];
                float q0a = fmaxf(fmaf(x02, wc0, fmaf(x01, wb0, fmaf(x00, wa0, ba))), 0.f);
                float q0b = fmaxf(fmaf(x02, wc1, fmaf(x01, wb1, fmaf(x00, wa1, bb))), 0.f);
                float q1a = fmaxf(fmaf(x12, wc0, fmaf(x11, wb0, fmaf(x10, wa0, ba))), 0.f);
                float q1b = fmaxf(fmaf(x12, wc1, fmaf(x11, wb1, fmaf(x10, wa1, bb))), 0.f);
                float q2a = fmaxf(fmaf(x22, wc0, fmaf(x21, wb0, fmaf(x20, wa0, ba))), 0.f);
                float q2b = fmaxf(fmaf(x22, wc1, fmaf(x21, wb1, fmaf(x20, wa1, bb))), 0.f);
                float q3a = fmaxf(fmaf(x32, wc0, fmaf(x31, wb0, fmaf(x30, wa0, ba))), 0.f);
                float q3b = fmaxf(fmaf(x32, wc1, fmaf(x31, wb1, fmaf(x30, wa1, bb))), 0.f);
                A0[ks][0 + h * 2] = f2h2(q0a, q0b);
                A0[ks][1 + h * 2] = f2h2(q1a, q1b);
                A1[ks][0 + h * 2] = f2h2(q2a, q2b);
                A1[ks][1 + h * 2] = f2h2(q3a, q3b);
            }
        }

        float acc3a[8][4], acc3b[8][4];
        #pragma unroll
        for (int n = 0; n < 8; n++)
            #pragma unroll
            for (int q = 0; q < 4; q++) { acc3a[n][q] = 0.f; acc3b[n][q] = 0.f; }

        #pragma unroll 1
        for (int nc = 0; nc < 4; nc++) {
            const uint32_t* w2p = sm + SW2 + nc * 4096 + lane * 2;
            const uint32_t* w3p = sm + SW3 + nc * 2048 + lane * 2;
            #pragma unroll
            for (int kt = 0; kt < 4; kt++) {
                int ntA = 2 * kt, ntB = 2 * kt + 1;
                float aA0[4] = {0,0,0,0}, aB0[4] = {0,0,0,0};
                float aA1[4] = {0,0,0,0}, aB1[4] = {0,0,0,0};
                #pragma unroll
                for (int ks = 0; ks < 8; ks++) {
                    uint2 bA = *(const uint2*)(w2p + (ks * 8 + ntA) * 64);
                    mma16(aA0, A0[ks], bA.x, bA.y);
                    mma16(aA1, A1[ks], bA.x, bA.y);
                    uint2 bB = *(const uint2*)(w2p + (ks * 8 + ntB) * 64);
                    mma16(aB0, A0[ks], bB.x, bB.y);
                    mma16(aB1, A1[ks], bB.x, bB.y);
                }
                float bA0 = smf[SB2 + nc * 64 + ntA * 8 + 2 * tig];
                float bA1 = smf[SB2 + nc * 64 + ntA * 8 + 2 * tig + 1];
                float bB0 = smf[SB2 + nc * 64 + ntB * 8 + 2 * tig];
                float bB1 = smf[SB2 + nc * 64 + ntB * 8 + 2 * tig + 1];
                uint32_t af0[4], af1[4];
                af0[0] = f2h2(fmaxf(aA0[0] + bA0, 0.f), fmaxf(aA0[1] + bA1, 0.f));
                af0[1] = f2h2(fmaxf(aA0[2] + bA0, 0.f), fmaxf(aA0[3] + bA1, 0.f));
                af0[2] = f2h2(fmaxf(aB0[0] + bB0, 0.f), fmaxf(aB0[1] + bB1, 0.f));
                af0[3] = f2h2(fmaxf(aB0[2] + bB0, 0.f), fmaxf(aB0[3] + bB1, 0.f));
                af1[0] = f2h2(fmaxf(aA1[0] + bA0, 0.f), fmaxf(aA1[1] + bA1, 0.f));
                af1[1] = f2h2(fmaxf(aA1[2] + bA0, 0.f), fmaxf(aA1[3] + bA1, 0.f));
                af1[2] = f2h2(fmaxf(aB1[0] + bB0, 0.f), fmaxf(aB1[1] + bB1, 0.f));
                af1[3] = f2h2(fmaxf(aB1[2] + bB0, 0.f), fmaxf(aB1[3] + bB1, 0.f));
                #pragma unroll
                for (int nt3 = 0; nt3 < 8; nt3++) {
                    uint2 b = *(const uint2*)(w3p + (kt * 8 + nt3) * 64);
                    mma16(acc3a[nt3], af0, b.x, b.y);
                    mma16(acc3b[nt3], af1, b.x, b.y);
                }
            }
        }

        // ---- epilogue: +b3; solo fast STG, else sign-split atomics ----
        #pragma unroll
        for (int sel = 0; sel < 4; sel++) {
            int r = (sel == 0) ? r0 : (sel == 1) ? r1 : (sel == 2) ? r2 : r3;
            const float (*acc)[4] = (sel < 2) ? acc3a : acc3b;
            int half = sel & 1;
            size_t rb = (size_t)(r >> 1) * 64;
            if (r & 1) {
                float* dst = pooled + rb;
                #pragma unroll
                for (int nt3 = 0; nt3 < 8; nt3++) {
                    int col = nt3 * 8 + 2 * tig;
                    float2 val;
                    val.x = acc[nt3][2 * half]     + smf[SB3 + col];
                    val.y = acc[nt3][2 * half + 1] + smf[SB3 + col + 1];
                    *(float2*)(dst + col) = val;
                }
            } else {
                float* dst = pooled + rb;
                #pragma unroll
                for (int nt3 = 0; nt3 < 8; nt3++) {
                    int col = nt3 * 8 + 2 * tig;
                    atomic_fmax(dst + col,     acc[nt3][2 * half]     + smf[SB3 + col]);
                    atomic_fmax(dst + col + 1, acc[nt3][2 * half + 1] + smf[SB3 + col + 1]);
                }
            }
        }
    }
}

// ---------------- host launcher ----------------
extern "C" void kernel_launch(void* const* d_in, const int* in_sizes, int n_in,
                              void* d_out, int out_size) {
    const float* pt_fea = (const float*)d_in[0];
    const int*   xy     = (const int*)d_in[1];
    const float* W1     = (const float*)d_in[2];
    const float* b1     = (const float*)d_in[3];
    const float* W2     = (const float*)d_in[4];
    const float* b2     = (const float*)d_in[5];
    const float* W3     = (const float*)d_in[6];
    const float* b3     = (const float*)d_in[7];

    int M;
    float* unq_out;
    float* pooled;
    if (out_size % 67 == 0) {
        M = out_size / 67;
        unq_out = (float*)d_out;
        pooled = (float*)d_out + (size_t)3 * M;
    } else {
        M = out_size / 64;
        unq_out = nullptr;
        pooled = (float*)d_out;
    }

    cudaFuncSetAttribute(k_mlp, cudaFuncAttributeMaxDynamicSharedMemorySize, SMEM_BYTES);

    k_mark<<<(PTOT + 255) / 256, 256>>>(xy);
    k_scan1<<<NCELL / 1024, 1024>>>();
    k_scan3<<<NCELL / 1024, 1024>>>(unq_out, (uint2*)pooled);
    k_mlp<<<NSM, NTHR, SMEM_BYTES>>>(pt_fea, xy, W1, b1, W2, b2, W3, b3, pooled);
}